// round 1
// baseline (speedup 1.0000x reference)
#include <cuda_runtime.h>
#include <math.h>

// ---------------------------------------------------------------------------
// ConnectedFilterLayerWithImplicitJacobian
//   logits = attrs2d @ w + b ; filtered = residues * sigmoid(logits)
//   delta[tpre[i]] = filtered[i]; delta[tpost[i]] = -filtered[i]   (permutation!)
//   cumsum = inclusive prefix sum of delta (length 2N)
//   out[p] = cumsum[tpre[node_of_pixel[p]]]
// ---------------------------------------------------------------------------

#define TMAX   (1 << 20)     // 2N = 1,000,000 <= 1,048,576
#define TILE   4096
#define SBLOCK 256
#define IPT    (TILE / SBLOCK)   // 16

__device__ float  g_delta[TMAX];
__device__ float  g_cumsum[TMAX];
__device__ double g_bsum[1024];
__device__ double g_boff[1024];

// ------------------------- kernel 1: filtered + scatter --------------------
__global__ void k_filtered(const float* __restrict__ weight,
                           const float* __restrict__ bias,
                           const float* __restrict__ residues,
                           const float* __restrict__ attrs,
                           const int*   __restrict__ tpre,
                           const int*   __restrict__ tpost,
                           int n)
{
    int i = blockIdx.x * blockDim.x + threadIdx.x;
    if (i >= n) return;

    const float4* a = reinterpret_cast<const float4*>(attrs + (size_t)i * 8);
    float4 a0 = a[0];
    float4 a1 = a[1];
    float4 w0 = *reinterpret_cast<const float4*>(weight);
    float4 w1 = *(reinterpret_cast<const float4*>(weight) + 1);

    float logit = a0.x * w0.x + a0.y * w0.y + a0.z * w0.z + a0.w * w0.w
                + a1.x * w1.x + a1.y * w1.y + a1.z * w1.z + a1.w * w1.w
                + bias[0];
    float s = 1.0f / (1.0f + expf(-logit));
    float f = residues[i] * s;

    // tpre ∪ tpost is a permutation of [0, 2N): plain stores, no atomics.
    g_delta[tpre[i]]  =  f;
    g_delta[tpost[i]] = -f;
}

// ------------------------- warp/block scan helpers (double) ----------------
__device__ __forceinline__ double warp_incl_scan(double v)
{
    int lane = threadIdx.x & 31;
#pragma unroll
    for (int o = 1; o < 32; o <<= 1) {
        double n = __shfl_up_sync(0xffffffffu, v, o);
        if (lane >= o) v += n;
    }
    return v;
}

// ------------------------- kernel 2: per-tile sums -------------------------
__global__ void k_tilesum(int T)
{
    int base = blockIdx.x * TILE;
    double s = 0.0;
    for (int j = threadIdx.x; j < TILE; j += blockDim.x) {
        int g = base + j;
        if (g < T) s += (double)g_delta[g];
    }
    // block reduce
    __shared__ double ws[SBLOCK / 32];
    int lane = threadIdx.x & 31, w = threadIdx.x >> 5;
#pragma unroll
    for (int o = 16; o > 0; o >>= 1)
        s += __shfl_down_sync(0xffffffffu, s, o);
    if (lane == 0) ws[w] = s;
    __syncthreads();
    if (threadIdx.x == 0) {
        double tot = 0.0;
        for (int k = 0; k < SBLOCK / 32; k++) tot += ws[k];
        g_bsum[blockIdx.x] = tot;
    }
}

// ------------------------- kernel 3: scan of block sums (1 block) ----------
__global__ void k_scanb(int nb)
{
    // nb <= 256 for this problem (ceil(1e6/4096) = 245)
    int t = threadIdx.x;
    double v = (t < nb) ? g_bsum[t] : 0.0;

    __shared__ double ws[SBLOCK / 32];
    int lane = t & 31, w = t >> 5;
    double incl = warp_incl_scan(v);
    if (lane == 31) ws[w] = incl;
    __syncthreads();
    if (w == 0) {
        double x = (lane < SBLOCK / 32) ? ws[lane] : 0.0;
        x = warp_incl_scan(x);
        if (lane < SBLOCK / 32) ws[lane] = x;
    }
    __syncthreads();
    double excl = incl - v + (w > 0 ? ws[w - 1] : 0.0);
    if (t < nb) g_boff[t] = excl;
}

// ------------------------- kernel 4: downsweep ------------------------------
__global__ void k_scandown(int T)
{
    __shared__ float  sh[TILE];
    __shared__ double wsum[SBLOCK / 32];

    int base = blockIdx.x * TILE;
    for (int j = threadIdx.x; j < TILE; j += blockDim.x) {
        int g = base + j;
        sh[j] = (g < T) ? g_delta[g] : 0.0f;
    }
    __syncthreads();

    int t = threadIdx.x;
    double s = 0.0;
#pragma unroll
    for (int j = 0; j < IPT; j++) s += (double)sh[t * IPT + j];

    // block exclusive scan of per-thread sums
    int lane = t & 31, w = t >> 5;
    double incl = warp_incl_scan(s);
    if (lane == 31) wsum[w] = incl;
    __syncthreads();
    if (w == 0) {
        double x = (lane < SBLOCK / 32) ? wsum[lane] : 0.0;
        x = warp_incl_scan(x);
        if (lane < SBLOCK / 32) wsum[lane] = x;
    }
    __syncthreads();
    double excl = incl - s + (w > 0 ? wsum[w - 1] : 0.0);

    double run = g_boff[blockIdx.x] + excl;
    float  tmp[IPT];
#pragma unroll
    for (int j = 0; j < IPT; j++) {
        run += (double)sh[t * IPT + j];
        tmp[j] = (float)run;
    }
    __syncthreads();
#pragma unroll
    for (int j = 0; j < IPT; j++) sh[t * IPT + j] = tmp[j];
    __syncthreads();

    for (int j = threadIdx.x; j < TILE; j += blockDim.x) {
        int g = base + j;
        if (g < T) g_cumsum[g] = sh[j];
    }
}

// ------------------------- kernel 5: per-pixel gather -----------------------
__global__ void k_gather(const int* __restrict__ nop,
                         const int* __restrict__ tpre,
                         float* __restrict__ out,
                         int P)
{
    int i = blockIdx.x * blockDim.x + threadIdx.x;
    int g = i * 4;
    if (g + 3 < P) {
        int4 n = *reinterpret_cast<const int4*>(nop + g);
        float4 r;
        r.x = g_cumsum[__ldg(tpre + n.x)];
        r.y = g_cumsum[__ldg(tpre + n.y)];
        r.z = g_cumsum[__ldg(tpre + n.z)];
        r.w = g_cumsum[__ldg(tpre + n.w)];
        *reinterpret_cast<float4*>(out + g) = r;
    } else {
        for (int j = g; j < P; j++)
            out[j] = g_cumsum[__ldg(tpre + nop[j])];
    }
}

// ---------------------------------------------------------------------------
extern "C" void kernel_launch(void* const* d_in, const int* in_sizes, int n_in,
                              void* d_out, int out_size)
{
    const float* weight   = (const float*)d_in[0];
    const float* bias     = (const float*)d_in[1];
    const float* residues = (const float*)d_in[2];
    const float* attrs    = (const float*)d_in[3];
    const int*   tpre     = (const int*)d_in[4];
    const int*   tpost    = (const int*)d_in[5];
    const int*   nop      = (const int*)d_in[6];

    int N = in_sizes[2];
    int P = in_sizes[6];
    int T = 2 * N;
    int nb = (T + TILE - 1) / TILE;

    k_filtered<<<(N + 255) / 256, 256>>>(weight, bias, residues, attrs, tpre, tpost, N);
    k_tilesum<<<nb, SBLOCK>>>(T);
    k_scanb<<<1, SBLOCK>>>(nb);
    k_scandown<<<nb, SBLOCK>>>(T);

    int gthreads = (P + 3) / 4;
    k_gather<<<(gthreads + 255) / 256, 256>>>(nop, tpre, (float*)d_out, P);
}

// round 2
// speedup vs baseline: 1.6230x; 1.6230x over previous
#include <cuda_runtime.h>
#include <math.h>

// ---------------------------------------------------------------------------
// ConnectedFilterLayerWithImplicitJacobian
//   filtered = residues * sigmoid(attrs2d @ w + b)
//   delta[tpre[i]] = filtered[i]; delta[tpost[i]] = -filtered[i]  (permutation)
//   cumsum = inclusive prefix sum of delta (length 2N)  [single-pass lookback]
//   y_node[i] = cumsum[tpre[i]]                         [per-node gather]
//   out[p]    = y_node[node_of_pixel[p]]                [per-pixel gather]
// ---------------------------------------------------------------------------

#define TMAX   (1 << 20)          // 2N = 1,000,000 <= 1,048,576
#define NMAX   (1 << 19)          // N = 500,000 <= 524,288
#define TILE   4096
#define SBLOCK 256

__device__ float g_delta[TMAX];
__device__ float g_cumsum[TMAX];
__device__ float g_ynode[NMAX];
// [0] = ticket counter, [1..] = lookback descriptors (flag<<32 | float bits)
__device__ unsigned long long g_scan_state[512];

#define FLAG_AGG 1u
#define FLAG_PRE 2u

__device__ __forceinline__ unsigned long long pack_desc(float v, unsigned f) {
    return ((unsigned long long)f << 32) | (unsigned long long)__float_as_uint(v);
}

// ------------------------- kernel 1: filtered + scatter --------------------
__global__ void k_filtered(const float* __restrict__ weight,
                           const float* __restrict__ bias,
                           const float* __restrict__ residues,
                           const float* __restrict__ attrs,
                           const int*   __restrict__ tpre,
                           const int*   __restrict__ tpost,
                           int n)
{
    int i = blockIdx.x * blockDim.x + threadIdx.x;
    if (i >= n) return;

    const float4* a = reinterpret_cast<const float4*>(attrs + (size_t)i * 8);
    float4 a0 = a[0];
    float4 a1 = a[1];
    float4 w0 = *reinterpret_cast<const float4*>(weight);
    float4 w1 = *(reinterpret_cast<const float4*>(weight) + 1);

    float logit = a0.x * w0.x + a0.y * w0.y + a0.z * w0.z + a0.w * w0.w
                + a1.x * w1.x + a1.y * w1.y + a1.z * w1.z + a1.w * w1.w
                + bias[0];
    float s = 1.0f / (1.0f + expf(-logit));
    float f = residues[i] * s;

    // tpre ∪ tpost is a permutation of [0, 2N): plain stores, no atomics.
    g_delta[tpre[i]]  =  f;
    g_delta[tpost[i]] = -f;
}

// ------------------------- kernel 2: single-pass lookback scan -------------
__global__ void k_scan(int T)
{
    __shared__ unsigned s_bid;
    __shared__ float    s_excl;
    __shared__ float    s_warp[SBLOCK / 32];

    int t = threadIdx.x;
    int lane = t & 31;
    int w = t >> 5;

    if (t == 0) s_bid = atomicAdd((unsigned int*)&g_scan_state[0], 1u);
    __syncthreads();
    int b = (int)s_bid;
    unsigned long long* desc = g_scan_state + 1;

    int base = b * TILE;
    bool full = (base + TILE <= T);

    // Load 16 contiguous floats per thread
    float e[16];
    if (full) {
        const float4* src = reinterpret_cast<const float4*>(g_delta + base + t * 16);
        float4 q0 = src[0], q1 = src[1], q2 = src[2], q3 = src[3];
        e[0]=q0.x; e[1]=q0.y; e[2]=q0.z; e[3]=q0.w;
        e[4]=q1.x; e[5]=q1.y; e[6]=q1.z; e[7]=q1.w;
        e[8]=q2.x; e[9]=q2.y; e[10]=q2.z; e[11]=q2.w;
        e[12]=q3.x; e[13]=q3.y; e[14]=q3.z; e[15]=q3.w;
    } else {
#pragma unroll
        for (int j = 0; j < 16; j++) {
            int g = base + t * 16 + j;
            e[j] = (g < T) ? g_delta[g] : 0.0f;
        }
    }

    // Serial inclusive scan within thread
    float run = 0.0f;
#pragma unroll
    for (int j = 0; j < 16; j++) { run += e[j]; e[j] = run; }

    // Warp inclusive scan of per-thread totals
    float incl = run;
#pragma unroll
    for (int o = 1; o < 32; o <<= 1) {
        float nb = __shfl_up_sync(0xffffffffu, incl, o);
        if (lane >= o) incl += nb;
    }
    if (lane == 31) s_warp[w] = incl;
    __syncthreads();
    if (t == 0) {
        float acc = 0.0f;
#pragma unroll
        for (int k = 0; k < SBLOCK / 32; k++) { acc += s_warp[k]; s_warp[k] = acc; }
    }
    __syncthreads();
    float thr_excl = incl - run + (w > 0 ? s_warp[w - 1] : 0.0f);
    float block_total = s_warp[SBLOCK / 32 - 1];

    // Publish aggregate (block 0 publishes final prefix directly)
    if (t == 0) {
        unsigned long long d = (b == 0) ? pack_desc(block_total, FLAG_PRE)
                                        : pack_desc(block_total, FLAG_AGG);
        atomicExch(&desc[b], d);
        if (b == 0) s_excl = 0.0f;
    }

    // Warp-parallel lookback (warp 0)
    if (b > 0 && w == 0) {
        float running = 0.0f;
        int tile_idx = b - 1;
        while (true) {
            int idx = tile_idx - lane;
            unsigned f;
            float val;
            if (idx < 0) { f = FLAG_PRE; val = 0.0f; }
            else {
                unsigned long long d;
                do {
                    d = *((volatile unsigned long long*)&desc[idx]);
                    f = (unsigned)(d >> 32);
                } while (f == 0u);
                val = __uint_as_float((unsigned)(d & 0xffffffffull));
            }
            unsigned pmask = __ballot_sync(0xffffffffu, f == FLAG_PRE);
            if (pmask) {
                int fp = __ffs(pmask) - 1;      // most recent tile holding a prefix
                float c = (lane <= fp) ? val : 0.0f;
#pragma unroll
                for (int o = 16; o > 0; o >>= 1) c += __shfl_xor_sync(0xffffffffu, c, o);
                running += c;
                break;
            } else {
                float c = val;
#pragma unroll
                for (int o = 16; o > 0; o >>= 1) c += __shfl_xor_sync(0xffffffffu, c, o);
                running += c;
                tile_idx -= 32;
            }
        }
        if (lane == 0) {
            s_excl = running;
            atomicExch(&desc[b], pack_desc(running + block_total, FLAG_PRE));
        }
    }
    __syncthreads();
    float add = s_excl + thr_excl;

    // Write results
    if (full) {
        float4* dst = reinterpret_cast<float4*>(g_cumsum + base + t * 16);
        float4 r;
        r.x=e[0]+add; r.y=e[1]+add; r.z=e[2]+add; r.w=e[3]+add;   dst[0]=r;
        r.x=e[4]+add; r.y=e[5]+add; r.z=e[6]+add; r.w=e[7]+add;   dst[1]=r;
        r.x=e[8]+add; r.y=e[9]+add; r.z=e[10]+add; r.w=e[11]+add; dst[2]=r;
        r.x=e[12]+add; r.y=e[13]+add; r.z=e[14]+add; r.w=e[15]+add; dst[3]=r;
    } else {
#pragma unroll
        for (int j = 0; j < 16; j++) {
            int g = base + t * 16 + j;
            if (g < T) g_cumsum[g] = e[j] + add;
        }
    }
}

// ------------------------- kernel 3: per-node gather ------------------------
__global__ void k_ynode(const int* __restrict__ tpre, int n)
{
    int i = (blockIdx.x * blockDim.x + threadIdx.x) * 4;
    if (i + 3 < n) {
        int4 tp = *reinterpret_cast<const int4*>(tpre + i);
        float4 r;
        r.x = g_cumsum[tp.x];
        r.y = g_cumsum[tp.y];
        r.z = g_cumsum[tp.z];
        r.w = g_cumsum[tp.w];
        *reinterpret_cast<float4*>(g_ynode + i) = r;
    } else {
        for (int j = i; j < n; j++) g_ynode[j] = g_cumsum[tpre[j]];
    }
}

// ------------------------- kernel 4: per-pixel gather -----------------------
__global__ void k_gather(const int* __restrict__ nop,
                         float* __restrict__ out,
                         int P)
{
    int i = (blockIdx.x * blockDim.x + threadIdx.x) * 8;
    if (i + 7 < P) {
        int4 n0 = *reinterpret_cast<const int4*>(nop + i);
        int4 n1 = *reinterpret_cast<const int4*>(nop + i + 4);
        float4 r0, r1;
        r0.x = g_ynode[n0.x];
        r0.y = g_ynode[n0.y];
        r0.z = g_ynode[n0.z];
        r0.w = g_ynode[n0.w];
        r1.x = g_ynode[n1.x];
        r1.y = g_ynode[n1.y];
        r1.z = g_ynode[n1.z];
        r1.w = g_ynode[n1.w];
        *reinterpret_cast<float4*>(out + i)     = r0;
        *reinterpret_cast<float4*>(out + i + 4) = r1;
    } else {
        for (int j = i; j < P; j++) out[j] = g_ynode[nop[j]];
    }
}

// ---------------------------------------------------------------------------
extern "C" void kernel_launch(void* const* d_in, const int* in_sizes, int n_in,
                              void* d_out, int out_size)
{
    const float* weight   = (const float*)d_in[0];
    const float* bias     = (const float*)d_in[1];
    const float* residues = (const float*)d_in[2];
    const float* attrs    = (const float*)d_in[3];
    const int*   tpre     = (const int*)d_in[4];
    const int*   tpost    = (const int*)d_in[5];
    const int*   nop      = (const int*)d_in[6];

    int N = in_sizes[2];
    int P = in_sizes[6];
    int T = 2 * N;
    int nb = (T + TILE - 1) / TILE;

    // Reset lookback state (ticket + descriptors) every launch — graph-safe.
    void* pstate = nullptr;
    cudaGetSymbolAddress(&pstate, g_scan_state);
    cudaMemsetAsync(pstate, 0, sizeof(unsigned long long) * (nb + 1));

    k_filtered<<<(N + 255) / 256, 256>>>(weight, bias, residues, attrs, tpre, tpost, N);
    k_scan<<<nb, SBLOCK>>>(T);

    int ynt = (N + 3) / 4;
    k_ynode<<<(ynt + 255) / 256, 256>>>(tpre, N);

    int gt = (P + 7) / 8;
    k_gather<<<(gt + 255) / 256, 256>>>(nop, (float*)d_out, P);
}